// round 8
// baseline (speedup 1.0000x reference)
#include <cuda_runtime.h>
#include <cuda_fp16.h>
#include <cuda_bf16.h>
#include <math.h>
#include <stdint.h>

#define S_LEN 2048
#define HIDDEN 6144
#define HD 128
#define NKVH 8
#define NG 6
#define NH 48

// bf16x3 split-K GEMM config (triplicated linear layout, R4 addressing)
#define K3 (3 * HIDDEN)          // 18432
#define NCH (K3 / 32)            // 576 BK=32 chunks
#define PITCHW 20                // smem row pitch in 32-bit words (40 bf16 = 80B)
#define NSTAGE 4
#define STG_A (256 * PITCHW * 4)               // 20480 B
#define STG_B (128 * PITCHW * 4)               // 10240 B
#define STAGE_BYTES (STG_A + STG_B)            // 30720
#define GEMM_SMEM (NSTAGE * STAGE_BYTES)       // 122880

typedef unsigned int u32;

// ---------------------------------------------------------------------------
// Device scratch
// ---------------------------------------------------------------------------
__device__ float g_qkv[33554432];                 // [2,2048,8,8,128] fp32
__device__ __nv_bfloat16 g_a3x[75497472];         // [4096, 18432]  [hi|hi|lo]
__device__ __nv_bfloat16 g_wqkv3[150994944];      // [8192, 18432]  [hi|lo|hi]
__device__ __nv_bfloat16 g_wo3[113246208];        // [6144, 18432]  [hi|lo|hi]
__device__ __nv_bfloat16 g_ctx3[75497472];        // [4096, 18432]  [hi|hi|lo]

__device__ __forceinline__ u32 smem_u32(const void* p) {
    u32 a;
    asm("{ .reg .u64 t; cvta.to.shared.u64 t, %1; cvt.u32.u64 %0, t; }" : "=r"(a) : "l"(p));
    return a;
}

#define CP16(d, s) \
    asm volatile("cp.async.cg.shared.global [%0], [%1], 16;" :: "r"(d), "l"(s))
#define CP_COMMIT() asm volatile("cp.async.commit_group;")
#define CP_WAIT(n)  asm volatile("cp.async.wait_group %0;" :: "n"(n))

#define LDSM4(R, addr) \
    asm volatile("ldmatrix.sync.aligned.m8n8.x4.shared.b16 {%0,%1,%2,%3}, [%4];" \
        : "=r"((R)[0]), "=r"((R)[1]), "=r"((R)[2]), "=r"((R)[3]) : "r"(addr))
#define LDSM4T(R, addr) \
    asm volatile("ldmatrix.sync.aligned.m8n8.x4.trans.shared.b16 {%0,%1,%2,%3}, [%4];" \
        : "=r"((R)[0]), "=r"((R)[1]), "=r"((R)[2]), "=r"((R)[3]) : "r"(addr))

__device__ __forceinline__ void mma_bf16(float* c, const u32* a, const u32* b) {
    asm volatile(
        "mma.sync.aligned.m16n8k16.row.col.f32.bf16.bf16.f32 "
        "{%0,%1,%2,%3}, {%4,%5,%6,%7}, {%8,%9}, {%0,%1,%2,%3};"
        : "+f"(c[0]), "+f"(c[1]), "+f"(c[2]), "+f"(c[3])
        : "r"(a[0]), "r"(a[1]), "r"(a[2]), "r"(a[3]), "r"(b[0]), "r"(b[1]));
}
__device__ __forceinline__ void mma_f16(float* c, const u32* a, const u32* b) {
    asm volatile(
        "mma.sync.aligned.m16n8k16.row.col.f32.f16.f16.f32 "
        "{%0,%1,%2,%3}, {%4,%5,%6,%7}, {%8,%9}, {%0,%1,%2,%3};"
        : "+f"(c[0]), "+f"(c[1]), "+f"(c[2]), "+f"(c[3])
        : "r"(a[0]), "r"(a[1]), "r"(a[2]), "r"(a[3]), "r"(b[0]), "r"(b[1]));
}

// ---------------------------------------------------------------------------
// Split fp32 -> bf16 (hi, lo): [hi|hi|lo] (left operand) / [hi|lo|hi] (right)
// ---------------------------------------------------------------------------
__global__ void split3_kernel(const float* __restrict__ in,
                              __nv_bfloat16* __restrict__ out,
                              int total4, int is_right) {
    int idx = blockIdx.x * blockDim.x + threadIdx.x;
    if (idx >= total4) return;
    float4 v = ((const float4*)in)[idx];
    int r = idx / (HIDDEN / 4);
    int c = (idx % (HIDDEN / 4)) * 4;
    float vv[4] = {v.x, v.y, v.z, v.w};
    unsigned hs[4], ls[4];
#pragma unroll
    for (int j = 0; j < 4; j++) {
        __nv_bfloat16 h = __float2bfloat16(vv[j]);
        __nv_bfloat16 l = __float2bfloat16(vv[j] - __bfloat162float(h));
        hs[j] = __bfloat16_as_ushort(h);
        ls[j] = __bfloat16_as_ushort(l);
    }
    uint2 hp = make_uint2(hs[0] | (hs[1] << 16), hs[2] | (hs[3] << 16));
    uint2 lp = make_uint2(ls[0] | (ls[1] << 16), ls[2] | (ls[3] << 16));
    __nv_bfloat16* row = out + (size_t)r * K3 + c;
    *(uint2*)row = hp;
    *(uint2*)(row + HIDDEN)     = is_right ? lp : hp;
    *(uint2*)(row + 2 * HIDDEN) = is_right ? hp : lp;
}

// ---------------------------------------------------------------------------
// bf16x3 HMMA GEMM: 256x128 CTA tile, 512 threads, 16 warps (64x32 each),
// BK=32, 4-stage cp.async ring, linear chunk addressing (R4 mainloop shape).
// ---------------------------------------------------------------------------
__global__ void __launch_bounds__(512, 1)
gemm_mma_kernel(const __nv_bfloat16* __restrict__ A,
                const __nv_bfloat16* __restrict__ B,
                float* __restrict__ C, int NT, int Ntot) {
    extern __shared__ __align__(16) u32 gsm[];
    const u32 gb = smem_u32(gsm);

    const int tid  = threadIdx.x;
    const int lane = tid & 31;
    const int wid  = tid >> 5;          // 0..15
    const int wm   = wid >> 2;          // 0..3
    const int wn   = wid & 3;           // 0..3

    // raster: groups of 8 m-tiles (2048 rows) per n sweep
    int bid = blockIdx.x;
    int gsz = 8 * NT;
    int g = bid / gsz, r = bid % gsz;
    int mt = g * 8 + (r & 7);
    int nt = r >> 3;
    int bm = mt * 256, bn = nt * 128;

    // global load mapping
    //   A: 256 rows x 64B: thread -> row tid>>1, 32B pair (tid&1)*32 (2 CP16)
    //   B: 128 rows x 64B: thread -> row tid>>2, 16B chunk (tid&3)   (1 CP16)
    const int arow = tid >> 1;
    const int acp  = tid & 1;
    const int brow = tid >> 2;
    const int bcp  = tid & 3;
    const __nv_bfloat16* Ag = A + (size_t)(bm + arow) * K3 + acp * 16;
    const __nv_bfloat16* Bg = B + (size_t)(bn + brow) * K3 + bcp * 8;
    const u32 a_doff = (u32)(arow * PITCHW * 4 + acp * 32);
    const u32 b_doff = (u32)(brow * PITCHW * 4 + bcp * 16);

    float acc[4][4][4];
#pragma unroll
    for (int mi = 0; mi < 4; mi++)
#pragma unroll
        for (int ni = 0; ni < 4; ni++)
#pragma unroll
            for (int q = 0; q < 4; q++) acc[mi][ni][q] = 0.f;

    // ldmatrix fragment base offsets (stage-relative, bytes)
    const u32 a_off = (u32)((wm * 64 + (lane & 15)) * PITCHW + 4 * (lane >> 4)) * 4;
    const u32 b_off = (u32)((wn * 32 + (lane & 7) + 8 * (lane >> 4)) * PITCHW
                            + 4 * ((lane >> 3) & 1)) * 4;

    // prologue: stages 0..2
#pragma unroll
    for (int s = 0; s < NSTAGE - 1; s++) {
        u32 sA = gb + s * STAGE_BYTES;
        u32 sB = sA + STG_A;
        const __nv_bfloat16* ga = Ag + (size_t)s * 32;
        const __nv_bfloat16* gp = Bg + (size_t)s * 32;
        CP16(sA + a_doff,      ga);
        CP16(sA + a_doff + 16, ga + 8);
        CP16(sB + b_doff,      gp);
        CP_COMMIT();
    }

    for (int c = 0; c < NCH; c++) {
        CP_WAIT(2);
        __syncthreads();
        if (c + NSTAGE - 1 < NCH) {
            int s = (c + NSTAGE - 1) & (NSTAGE - 1);
            u32 sA = gb + s * STAGE_BYTES;
            u32 sB = sA + STG_A;
            const __nv_bfloat16* ga = Ag + (size_t)(c + NSTAGE - 1) * 32;
            const __nv_bfloat16* gp = Bg + (size_t)(c + NSTAGE - 1) * 32;
            CP16(sA + a_doff,      ga);
            CP16(sA + a_doff + 16, ga + 8);
            CP16(sB + b_doff,      gp);
        }
        CP_COMMIT();

        u32 stA = gb + (c & (NSTAGE - 1)) * STAGE_BYTES;
        u32 stB = stA + STG_A;
#pragma unroll
        for (int ks = 0; ks < 2; ks++) {
            u32 a[4][4];
#pragma unroll
            for (int mi = 0; mi < 4; mi++)
                LDSM4(a[mi], stA + a_off + mi * (16 * PITCHW * 4) + ks * 32);
#pragma unroll
            for (int np = 0; np < 2; np++) {
                u32 bb[4];
                LDSM4(bb, stB + b_off + np * (16 * PITCHW * 4) + ks * 32);
#pragma unroll
                for (int mi = 0; mi < 4; mi++) {
                    mma_bf16(acc[mi][2 * np],     a[mi], bb);
                    mma_bf16(acc[mi][2 * np + 1], a[mi], bb + 2);
                }
            }
        }
    }

    // epilogue
    const int lr = lane >> 2;
    const int lq = lane & 3;
#pragma unroll
    for (int mi = 0; mi < 4; mi++) {
        int row = bm + wm * 64 + mi * 16 + lr;
#pragma unroll
        for (int ni = 0; ni < 4; ni++) {
            int col = bn + wn * 32 + ni * 8 + lq * 2;
            float* p0 = C + (size_t)row * Ntot + col;
            *(float2*)p0 = make_float2(acc[mi][ni][0], acc[mi][ni][1]);
            *(float2*)(p0 + (size_t)8 * Ntot) = make_float2(acc[mi][ni][2], acc[mi][ni][3]);
        }
    }
}

// ---------------------------------------------------------------------------
// RoPE in-place on q heads (slots 0..5) and k (slot 6)
// ---------------------------------------------------------------------------
__global__ void rope_kernel(float* __restrict__ qkv) {
    int idx = blockIdx.x * blockDim.x + threadIdx.x;
    if (idx >= 4096 * 8 * 7 * 64) return;
    int i = idx & 63;
    int t = idx >> 6;
    int slot = t % 7;
    t /= 7;
    int kvh = t & 7;
    int bs = t >> 3;
    int s = bs & (S_LEN - 1);
    float inv = exp2f(-(float)i * (19.931568569324174f / 64.0f));
    float f = (float)s * inv;
    float c = cosf(f), sn = sinf(f);
    float* p = qkv + (((size_t)bs * NKVH + kvh) * 8 + slot) * HD;
    float a = p[i], b = p[i + 64];
    p[i]      = a * c - b * sn;
    p[i + 64] = b * c + a * sn;
}

// ---------------------------------------------------------------------------
// Flash attention on tensor cores, fp16 hi/lo split (3-term), causal, GQA.
// BQ=128, BK=64, 256 threads; epilogue writes triplicated ctx3 bf16 directly.
// ---------------------------------------------------------------------------
#define QP2 136
#define ATTN_SMEM ((128 * 2 + 64 * 4) * QP2 * 2)   // 139264 bytes

__device__ __forceinline__ u32 pack_h2(float lo, float hi) {
    u32 r;
    asm("cvt.rn.f16x2.f32 %0, %1, %2;" : "=r"(r) : "f"(hi), "f"(lo));
    return r;
}

__global__ void __launch_bounds__(256, 1)
attn_mma_kernel(const float* __restrict__ qkv, __nv_bfloat16* __restrict__ ctx3) {
    extern __shared__ __align__(16) __half hsm[];
    __half* Qh = hsm;
    __half* Ql = Qh + 128 * QP2;
    __half* Kh = Ql + 128 * QP2;
    __half* Kl = Kh + 64 * QP2;
    __half* Vh = Kl + 64 * QP2;
    __half* Vl = Vh + 64 * QP2;

    const int tid  = threadIdx.x;
    const int lane = tid & 31;
    const int wid  = tid >> 5;
    const int qt   = (int)gridDim.x - 1 - blockIdx.x;   // heavy tiles first
    const int h    = blockIdx.y;
    const int b    = blockIdx.z;
    const int kvh  = h / NG, slot = h % NG;
    const int qbase = qt * 128;
    const float scale = 0.08838834764831845f;

    // --- load Q tile (scaled), split hi/lo fp16 ---
#pragma unroll
    for (int it = 0; it < 16; it++) {
        int v = tid + it * 256;
        int row = v >> 5, c4 = v & 31;
        const float* g = qkv + ((((size_t)b * S_LEN + qbase + row) * NKVH + kvh) * 8 + slot) * HD + c4 * 4;
        float4 q = *(const float4*)g;
        float f[4] = {q.x * scale, q.y * scale, q.z * scale, q.w * scale};
        __half hh[4]; float rl[4];
#pragma unroll
        for (int j = 0; j < 4; j++) {
            hh[j] = __float2half_rn(f[j]);
            rl[j] = f[j] - __half2float(hh[j]);
        }
        __half2* dh = (__half2*)&Qh[row * QP2 + c4 * 4];
        dh[0] = __halves2half2(hh[0], hh[1]);
        dh[1] = __halves2half2(hh[2], hh[3]);
        __half2* dl = (__half2*)&Ql[row * QP2 + c4 * 4];
        dl[0] = __halves2half2(__float2half_rn(rl[0]), __float2half_rn(rl[1]));
        dl[1] = __halves2half2(__float2half_rn(rl[2]), __float2half_rn(rl[3]));
    }

    float S[8][4], O[16][4];
    float m0 = -INFINITY, m1 = -INFINITY, l0 = 0.f, l1 = 0.f;
#pragma unroll
    for (int nj = 0; nj < 16; nj++)
#pragma unroll
        for (int q = 0; q < 4; q++) O[nj][q] = 0.f;

    const u32 qh_b = smem_u32(Qh), ql_b = smem_u32(Ql);
    const u32 kh_b = smem_u32(Kh), kl_b = smem_u32(Kl);
    const u32 vh_b = smem_u32(Vh), vl_b = smem_u32(Vl);
    const u32 a_off = ((u32)(wid * 16 + (lane & 15)) * QP2 + 8 * (lane >> 4)) * 2;
    const u32 b_off = ((u32)((lane & 7) + 8 * (lane >> 4)) * QP2 + 8 * ((lane >> 3) & 1)) * 2;
    const u32 v_off = ((u32)((lane & 7) + 8 * ((lane >> 3) & 1)) * QP2 + 8 * (lane >> 4)) * 2;

    const int nkt = 2 * qt + 2;
    for (int kt = 0; kt < nkt; kt++) {
        __syncthreads();
        // --- load K/V tile, split hi/lo ---
#pragma unroll
        for (int it = 0; it < 8; it++) {
            int v = tid + it * 256;
            int row = v >> 5, c4 = v & 31;
            size_t gbse = (((size_t)b * S_LEN + kt * 64 + row) * NKVH + kvh) * 8;
            float4 kk = *(const float4*)(qkv + (gbse + NG) * HD + c4 * 4);
            float4 vv = *(const float4*)(qkv + (gbse + NG + 1) * HD + c4 * 4);
            float fk[4] = {kk.x, kk.y, kk.z, kk.w};
            float fv[4] = {vv.x, vv.y, vv.z, vv.w};
            __half kh4[4], vh4[4]; float krl[4], vrl[4];
#pragma unroll
            for (int j = 0; j < 4; j++) {
                kh4[j] = __float2half_rn(fk[j]); krl[j] = fk[j] - __half2float(kh4[j]);
                vh4[j] = __float2half_rn(fv[j]); vrl[j] = fv[j] - __half2float(vh4[j]);
            }
            int so = row * QP2 + c4 * 4;
            ((__half2*)&Kh[so])[0] = __halves2half2(kh4[0], kh4[1]);
            ((__half2*)&Kh[so])[1] = __halves2half2(kh4[2], kh4[3]);
            ((__half2*)&Kl[so])[0] = __halves2half2(__float2half_rn(krl[0]), __float2half_rn(krl[1]));
            ((__half2*)&Kl[so])[1] = __halves2half2(__float2half_rn(krl[2]), __float2half_rn(krl[3]));
            ((__half2*)&Vh[so])[0] = __halves2half2(vh4[0], vh4[1]);
            ((__half2*)&Vh[so])[1] = __halves2half2(vh4[2], vh4[3]);
            ((__half2*)&Vl[so])[0] = __halves2half2(__float2half_rn(vrl[0]), __float2half_rn(vrl[1]));
            ((__half2*)&Vl[so])[1] = __halves2half2(__float2half_rn(vrl[2]), __float2half_rn(vrl[3]));
        }
        __syncthreads();

        // --- scores S = Q K^T (3-term split) ---
#pragma unroll
        for (int j = 0; j < 8; j++)
#pragma unroll
            for (int q = 0; q < 4; q++) S[j][q] = 0.f;

#pragma unroll
        for (int kc = 0; kc < 8; kc++) {
            u32 ah[4], al[4];
            LDSM4(ah, qh_b + a_off + kc * 32);
            LDSM4(al, ql_b + a_off + kc * 32);
#pragma unroll
            for (int nn = 0; nn < 4; nn++) {
                u32 bh[4], bl[4];
                u32 bo = b_off + nn * (16 * QP2 * 2) + kc * 32;
                LDSM4(bh, kh_b + bo);
                LDSM4(bl, kl_b + bo);
                mma_f16(S[2 * nn],     ah, bh);
                mma_f16(S[2 * nn],     ah, bl);
                mma_f16(S[2 * nn],     al, bh);
                mma_f16(S[2 * nn + 1], ah, bh + 2);
                mma_f16(S[2 * nn + 1], ah, bl + 2);
                mma_f16(S[2 * nn + 1], al, bh + 2);
            }
        }

        // --- causal mask (diagonal tiles only) ---
        if (kt >= 2 * qt) {
            int r0 = qbase + wid * 16 + (lane >> 2);
            int r1 = r0 + 8;
#pragma unroll
            for (int j = 0; j < 8; j++) {
                int c0 = kt * 64 + 8 * j + 2 * (lane & 3);
                if (c0 > r0)     S[j][0] = -1e30f;
                if (c0 + 1 > r0) S[j][1] = -1e30f;
                if (c0 > r1)     S[j][2] = -1e30f;
                if (c0 + 1 > r1) S[j][3] = -1e30f;
            }
        }

        // --- online softmax ---
        float rmax0 = -INFINITY, rmax1 = -INFINITY;
#pragma unroll
        for (int j = 0; j < 8; j++) {
            rmax0 = fmaxf(rmax0, fmaxf(S[j][0], S[j][1]));
            rmax1 = fmaxf(rmax1, fmaxf(S[j][2], S[j][3]));
        }
        rmax0 = fmaxf(rmax0, __shfl_xor_sync(0xffffffffu, rmax0, 1));
        rmax0 = fmaxf(rmax0, __shfl_xor_sync(0xffffffffu, rmax0, 2));
        rmax1 = fmaxf(rmax1, __shfl_xor_sync(0xffffffffu, rmax1, 1));
        rmax1 = fmaxf(rmax1, __shfl_xor_sync(0xffffffffu, rmax1, 2));
        float mn0 = fmaxf(m0, rmax0), mn1 = fmaxf(m1, rmax1);
        float al0 = __expf(m0 - mn0), al1 = __expf(m1 - mn1);
        float rs0 = 0.f, rs1 = 0.f;
#pragma unroll
        for (int j = 0; j < 8; j++) {
            S[j][0] = __expf(S[j][0] - mn0);
            S[j][1] = __expf(S[j][1] - mn0);
            S[j][2] = __expf(S[j][2] - mn1);
            S[j][3] = __expf(S[j][3] - mn1);
            rs0 += S[j][0] + S[j][1];
            rs1 += S[j][2] + S[j][3];
        }
        rs0 += __shfl_xor_sync(0xffffffffu, rs0, 1);
        rs0 += __shfl_xor_sync(0xffffffffu, rs0, 2);
        rs1 += __shfl_xor_sync(0xffffffffu, rs1, 1);
        rs1 += __shfl_xor_sync(0xffffffffu, rs1, 2);
        l0 = l0 * al0 + rs0;
        l1 = l1 * al1 + rs1;
        m0 = mn0; m1 = mn1;
#pragma unroll
        for (int nj = 0; nj < 16; nj++) {
            O[nj][0] *= al0; O[nj][1] *= al0;
            O[nj][2] *= al1; O[nj][3] *= al1;
        }

        // --- O += P V (3-term split, P frags in-register) ---
#pragma unroll
        for (int kc2 = 0; kc2 < 4; kc2++) {
            int j0 = 2 * kc2, j1 = 2 * kc2 + 1;
            u32 pa[4], pl[4];
            float e[4][2] = {{S[j0][0], S[j0][1]}, {S[j0][2], S[j0][3]},
                             {S[j1][0], S[j1][1]}, {S[j1][2], S[j1][3]}};
#pragma unroll
            for (int q = 0; q < 4; q++) {
                __half h0 = __float2half_rn(e[q][0]);
                __half h1 = __float2half_rn(e[q][1]);
                pa[q] = pack_h2((float)__half2float(h0), (float)__half2float(h1));
                pl[q] = pack_h2(e[q][0] - __half2float(h0), e[q][1] - __half2float(h1));
            }
#pragma unroll
            for (int nn = 0; nn < 8; nn++) {
                u32 vh[4], vl[4];
                u32 vo = v_off + kc2 * (16 * QP2 * 2) + nn * 32;
                LDSM4T(vh, vh_b + vo);
                LDSM4T(vl, vl_b + vo);
                mma_f16(O[2 * nn],     pa, vh);
                mma_f16(O[2 * nn],     pa, vl);
                mma_f16(O[2 * nn],     pl, vh);
                mma_f16(O[2 * nn + 1], pa, vh + 2);
                mma_f16(O[2 * nn + 1], pa, vl + 2);
                mma_f16(O[2 * nn + 1], pl, vh + 2);
            }
        }
    }

    // --- epilogue: normalize + write ctx3 bf16 [hi|hi|lo] directly ---
    float inv0 = 1.0f / l0, inv1 = 1.0f / l1;
    int r0 = qbase + wid * 16 + (lane >> 2);
    __nv_bfloat16* d0 = ctx3 + ((size_t)b * S_LEN + r0) * K3 + h * HD + 2 * (lane & 3);
    __nv_bfloat16* d1 = d0 + (size_t)8 * K3;
#pragma unroll
    for (int nj = 0; nj < 16; nj++) {
        float a0 = O[nj][0] * inv0, a1 = O[nj][1] * inv0;
        float b0 = O[nj][2] * inv1, b1 = O[nj][3] * inv1;
        __nv_bfloat16 ha0 = __float2bfloat16(a0), ha1 = __float2bfloat16(a1);
        __nv_bfloat16 hb0 = __float2bfloat16(b0), hb1 = __float2bfloat16(b1);
        u32 hp0 = (u32)__bfloat16_as_ushort(ha0) | ((u32)__bfloat16_as_ushort(ha1) << 16);
        u32 hp1 = (u32)__bfloat16_as_ushort(hb0) | ((u32)__bfloat16_as_ushort(hb1) << 16);
        u32 lp0 = (u32)__bfloat16_as_ushort(__float2bfloat16(a0 - __bfloat162float(ha0)))
                | ((u32)__bfloat16_as_ushort(__float2bfloat16(a1 - __bfloat162float(ha1))) << 16);
        u32 lp1 = (u32)__bfloat16_as_ushort(__float2bfloat16(b0 - __bfloat162float(hb0)))
                | ((u32)__bfloat16_as_ushort(__float2bfloat16(b1 - __bfloat162float(hb1))) << 16);
        *(u32*)(d0 + 8 * nj)              = hp0;
        *(u32*)(d0 + HIDDEN + 8 * nj)     = hp0;
        *(u32*)(d0 + 2 * HIDDEN + 8 * nj) = lp0;
        *(u32*)(d1 + 8 * nj)              = hp1;
        *(u32*)(d1 + HIDDEN + 8 * nj)     = hp1;
        *(u32*)(d1 + 2 * HIDDEN + 8 * nj) = lp1;
    }
}

// ---------------------------------------------------------------------------
extern "C" void kernel_launch(void* const* d_in, const int* in_sizes, int n_in,
                              void* d_out, int out_size) {
    const float* x    = (const float*)d_in[0];   // [2,2048,6144]
    const float* Wqkv = (const float*)d_in[1];   // [8192,6144]
    const float* Wo   = (const float*)d_in[2];   // [6144,6144]
    float* out = (float*)d_out;                  // [2,2048,6144]

    float* qkv = nullptr;
    __nv_bfloat16 *a3x = nullptr, *wqkv3 = nullptr, *wo3 = nullptr, *ctx3 = nullptr;
    cudaGetSymbolAddress((void**)&qkv,   g_qkv);
    cudaGetSymbolAddress((void**)&a3x,   g_a3x);
    cudaGetSymbolAddress((void**)&wqkv3, g_wqkv3);
    cudaGetSymbolAddress((void**)&wo3,   g_wo3);
    cudaGetSymbolAddress((void**)&ctx3,  g_ctx3);

    cudaFuncSetAttribute(gemm_mma_kernel,
                         cudaFuncAttributeMaxDynamicSharedMemorySize, GEMM_SMEM);
    cudaFuncSetAttribute(attn_mma_kernel,
                         cudaFuncAttributeMaxDynamicSharedMemorySize, ATTN_SMEM);

    // 0) bf16 hi/lo splits (triplicated linear layouts)
    int t4x = 4096 * (HIDDEN / 4);
    int t4q = 8192 * (HIDDEN / 4);
    int t4o = 6144 * (HIDDEN / 4);
    split3_kernel<<<(t4x + 255) / 256, 256>>>(x,    a3x,   t4x, 0);
    split3_kernel<<<(t4q + 255) / 256, 256>>>(Wqkv, wqkv3, t4q, 1);
    split3_kernel<<<(t4o + 255) / 256, 256>>>(Wo,   wo3,   t4o, 1);

    // 1) QKV projection: [4096,8192]  (MT=16 x NT=64 = 1024 CTAs)
    gemm_mma_kernel<<<16 * 64, 512, GEMM_SMEM>>>(a3x, wqkv3, qkv, 64, 8192);

    // 2) RoPE
    rope_kernel<<<(4096 * 8 * 7 * 64) / 256, 256>>>(qkv);

    // 3) Flash attention (tensor cores) -> ctx3 bf16 [hi|hi|lo] (split fused)
    attn_mma_kernel<<<dim3(16, NH, 2), 256, ATTN_SMEM>>>(qkv, ctx3);

    // 4) output projection: [4096,6144]  (MT=16 x NT=48 = 768 CTAs)
    gemm_mma_kernel<<<16 * 48, 512, GEMM_SMEM>>>(ctx3, wo3, out, 48, 6144);
}

// round 9
// speedup vs baseline: 1.1259x; 1.1259x over previous
#include <cuda_runtime.h>
#include <cuda_fp16.h>
#include <cuda_bf16.h>
#include <math.h>
#include <stdint.h>

#define S_LEN 2048
#define HIDDEN 6144
#define HD 128
#define NKVH 8
#define NG 6
#define NH 48

// bf16x3 split-K GEMM config (R4 frozen)
#define K3 (3 * HIDDEN)          // 18432
#define NCH (K3 / 32)            // 576 BK=32 chunks
#define PITCHW 20                // smem row pitch in 32-bit words (40 bf16 = 80B)
#define NSTAGE 4
#define STG_BYTES (128 * PITCHW * 4)           // 10240 per operand
#define STAGE_BYTES (2 * STG_BYTES)            // A + B
#define GEMM_SMEM (NSTAGE * STAGE_BYTES)       // 81920

typedef unsigned int u32;

// ---------------------------------------------------------------------------
// Device scratch
// ---------------------------------------------------------------------------
__device__ float g_qkv[33554432];                 // [2,2048,8,8,128] fp32
__device__ __nv_bfloat16 g_a3x[75497472];         // [4096, 18432]  [hi|hi|lo]
__device__ __nv_bfloat16 g_wqkv3[150994944];      // [8192, 18432]  [hi|lo|hi]
__device__ __nv_bfloat16 g_wo3[113246208];        // [6144, 18432]  [hi|lo|hi]
__device__ __nv_bfloat16 g_ctx3[75497472];        // [4096, 18432]  [hi|hi|lo]
__device__ __half g_q16[50331648];                // [2,48,2048,256]  qh|ql
__device__ __half g_kv16[16777216];               // [2,8,2048,512]   kh|kl|vh|vl

__device__ __forceinline__ u32 smem_u32(const void* p) {
    u32 a;
    asm("{ .reg .u64 t; cvta.to.shared.u64 t, %1; cvt.u32.u64 %0, t; }" : "=r"(a) : "l"(p));
    return a;
}

#define CP16(d, s) \
    asm volatile("cp.async.cg.shared.global [%0], [%1], 16;" :: "r"(d), "l"(s))
#define CP_COMMIT() asm volatile("cp.async.commit_group;")
#define CP_WAIT(n)  asm volatile("cp.async.wait_group %0;" :: "n"(n))

#define LDSM4(R, addr) \
    asm volatile("ldmatrix.sync.aligned.m8n8.x4.shared.b16 {%0,%1,%2,%3}, [%4];" \
        : "=r"((R)[0]), "=r"((R)[1]), "=r"((R)[2]), "=r"((R)[3]) : "r"(addr))
#define LDSM4T(R, addr) \
    asm volatile("ldmatrix.sync.aligned.m8n8.x4.trans.shared.b16 {%0,%1,%2,%3}, [%4];" \
        : "=r"((R)[0]), "=r"((R)[1]), "=r"((R)[2]), "=r"((R)[3]) : "r"(addr))

__device__ __forceinline__ void mma_bf16(float* c, const u32* a, const u32* b) {
    asm volatile(
        "mma.sync.aligned.m16n8k16.row.col.f32.bf16.bf16.f32 "
        "{%0,%1,%2,%3}, {%4,%5,%6,%7}, {%8,%9}, {%0,%1,%2,%3};"
        : "+f"(c[0]), "+f"(c[1]), "+f"(c[2]), "+f"(c[3])
        : "r"(a[0]), "r"(a[1]), "r"(a[2]), "r"(a[3]), "r"(b[0]), "r"(b[1]));
}
__device__ __forceinline__ void mma_f16(float* c, const u32* a, const u32* b) {
    asm volatile(
        "mma.sync.aligned.m16n8k16.row.col.f32.f16.f16.f32 "
        "{%0,%1,%2,%3}, {%4,%5,%6,%7}, {%8,%9}, {%0,%1,%2,%3};"
        : "+f"(c[0]), "+f"(c[1]), "+f"(c[2]), "+f"(c[3])
        : "r"(a[0]), "r"(a[1]), "r"(a[2]), "r"(a[3]), "r"(b[0]), "r"(b[1]));
}

// ---------------------------------------------------------------------------
// Split fp32 -> bf16 (hi, lo): [hi|hi|lo] (left operand) / [hi|lo|hi] (right)
// ---------------------------------------------------------------------------
__global__ void split3_kernel(const float* __restrict__ in,
                              __nv_bfloat16* __restrict__ out,
                              int total4, int is_right) {
    int idx = blockIdx.x * blockDim.x + threadIdx.x;
    if (idx >= total4) return;
    float4 v = ((const float4*)in)[idx];
    int r = idx / (HIDDEN / 4);
    int c = (idx % (HIDDEN / 4)) * 4;
    float vv[4] = {v.x, v.y, v.z, v.w};
    unsigned hs[4], ls[4];
#pragma unroll
    for (int j = 0; j < 4; j++) {
        __nv_bfloat16 h = __float2bfloat16(vv[j]);
        __nv_bfloat16 l = __float2bfloat16(vv[j] - __bfloat162float(h));
        hs[j] = __bfloat16_as_ushort(h);
        ls[j] = __bfloat16_as_ushort(l);
    }
    uint2 hp = make_uint2(hs[0] | (hs[1] << 16), hs[2] | (hs[3] << 16));
    uint2 lp = make_uint2(ls[0] | (ls[1] << 16), ls[2] | (ls[3] << 16));
    __nv_bfloat16* row = out + (size_t)r * K3 + c;
    *(uint2*)row = hp;
    *(uint2*)(row + HIDDEN)     = is_right ? lp : hp;
    *(uint2*)(row + 2 * HIDDEN) = is_right ? hp : lp;
}

// ---------------------------------------------------------------------------
// bf16x3 HMMA GEMM — R4 frozen: 128x128 tile, BK=32, 8 warps (64x32),
// 4-stage cp.async ring, ldmatrix frags, 2 CTAs/SM.
// ---------------------------------------------------------------------------
__global__ void __launch_bounds__(256, 2)
gemm_mma_kernel(const __nv_bfloat16* __restrict__ A,
                const __nv_bfloat16* __restrict__ B,
                float* __restrict__ C, int NT, int Ntot) {
    extern __shared__ __align__(16) u32 gsm[];
    const u32 gb = smem_u32(gsm);

    const int tid  = threadIdx.x;
    const int lane = tid & 31;
    const int wid  = tid >> 5;
    const int wm   = wid >> 2;          // 0..1
    const int wn   = wid & 3;           // 0..3

    int bid = blockIdx.x;
    int gsz = 8 * NT;
    int g = bid / gsz, r = bid % gsz;
    int mt = g * 8 + (r & 7);
    int nt = r >> 3;
    int bm = mt * 128, bn = nt * 128;

    const int grow = tid >> 2;
    const int gc16 = tid & 3;
    const __nv_bfloat16* Ag = A + (size_t)(bm + grow) * K3 + gc16 * 8;
    const __nv_bfloat16* Bg = B + (size_t)(bn + grow) * K3 + gc16 * 8;
    const u32 doff  = (u32)(grow * PITCHW + gc16 * 4) * 4;
    const u32 doff2 = doff + 64 * PITCHW * 4;

    float acc[4][4][4];
#pragma unroll
    for (int mi = 0; mi < 4; mi++)
#pragma unroll
        for (int ni = 0; ni < 4; ni++)
#pragma unroll
            for (int q = 0; q < 4; q++) acc[mi][ni][q] = 0.f;

    const u32 a_off = (u32)((wm * 64 + (lane & 15)) * PITCHW + 4 * (lane >> 4)) * 4;
    const u32 b_off = (u32)((wn * 32 + (lane & 7) + 8 * (lane >> 4)) * PITCHW
                            + 4 * ((lane >> 3) & 1)) * 4;

    // prologue: stages 0..2
#pragma unroll
    for (int s = 0; s < NSTAGE - 1; s++) {
        u32 sA = gb + s * STAGE_BYTES;
        u32 sB = sA + STG_BYTES;
        const __nv_bfloat16* ga = Ag + (size_t)s * 32;
        const __nv_bfloat16* gp = Bg + (size_t)s * 32;
        CP16(sA + doff,  ga);
        CP16(sA + doff2, ga + (size_t)64 * K3);
        CP16(sB + doff,  gp);
        CP16(sB + doff2, gp + (size_t)64 * K3);
        CP_COMMIT();
    }

    for (int c = 0; c < NCH; c++) {
        CP_WAIT(2);
        __syncthreads();
        if (c + NSTAGE - 1 < NCH) {
            int s = (c + NSTAGE - 1) & (NSTAGE - 1);
            u32 sA = gb + s * STAGE_BYTES;
            u32 sB = sA + STG_BYTES;
            const __nv_bfloat16* ga = Ag + (size_t)(c + NSTAGE - 1) * 32;
            const __nv_bfloat16* gp = Bg + (size_t)(c + NSTAGE - 1) * 32;
            CP16(sA + doff,  ga);
            CP16(sA + doff2, ga + (size_t)64 * K3);
            CP16(sB + doff,  gp);
            CP16(sB + doff2, gp + (size_t)64 * K3);
        }
        CP_COMMIT();

        u32 stA = gb + (c & (NSTAGE - 1)) * STAGE_BYTES;
        u32 stB = stA + STG_BYTES;
#pragma unroll
        for (int ks = 0; ks < 2; ks++) {
            u32 a[4][4];
#pragma unroll
            for (int mi = 0; mi < 4; mi++)
                LDSM4(a[mi], stA + a_off + mi * (16 * PITCHW * 4) + ks * 32);
#pragma unroll
            for (int np = 0; np < 2; np++) {
                u32 bb[4];
                LDSM4(bb, stB + b_off + np * (16 * PITCHW * 4) + ks * 32);
#pragma unroll
                for (int mi = 0; mi < 4; mi++) {
                    mma_bf16(acc[mi][2 * np],     a[mi], bb);
                    mma_bf16(acc[mi][2 * np + 1], a[mi], bb + 2);
                }
            }
        }
    }

    // epilogue
    const int lr = lane >> 2;
    const int lq = lane & 3;
#pragma unroll
    for (int mi = 0; mi < 4; mi++) {
        int row = bm + wm * 64 + mi * 16 + lr;
#pragma unroll
        for (int ni = 0; ni < 4; ni++) {
            int col = bn + wn * 32 + ni * 8 + lq * 2;
            float* p0 = C + (size_t)row * Ntot + col;
            *(float2*)p0 = make_float2(acc[mi][ni][0], acc[mi][ni][1]);
            *(float2*)(p0 + (size_t)8 * Ntot) = make_float2(acc[mi][ni][2], acc[mi][ni][3]);
        }
    }
}

// ---------------------------------------------------------------------------
// RoPE + scale + fp16 hi/lo split, writing q16 [b,h,s,256] and kv16 [b,kvh,s,512]
// ---------------------------------------------------------------------------
__global__ void rope16_kernel(const float* __restrict__ qkv,
                              __half* __restrict__ q16,
                              __half* __restrict__ kv16) {
    int idx = blockIdx.x * blockDim.x + threadIdx.x;
    if (idx >= 4096 * 8 * 8 * 64) return;
    int i = idx & 63;
    int t = idx >> 6;
    int slot = t & 7;
    t >>= 3;
    int kvh = t & 7;
    int bs = t >> 3;
    int b = bs >> 11;
    int s = bs & (S_LEN - 1);
    const float* p = qkv + (((size_t)bs * NKVH + kvh) * 8 + slot) * HD;
    float a = p[i], v2 = p[i + 64];
    float r0, r1;
    if (slot < 7) {
        float inv = exp2f(-(float)i * (19.931568569324174f / 64.0f));
        float f = (float)s * inv;
        float c = cosf(f), sn = sinf(f);
        r0 = a * c - v2 * sn;
        r1 = v2 * c + a * sn;
    } else {
        r0 = a; r1 = v2;
    }
    if (slot < 6) {
        r0 *= 0.08838834764831845f;
        r1 *= 0.08838834764831845f;
    }
    __half h0 = __float2half_rn(r0), h1 = __float2half_rn(r1);
    __half l0 = __float2half_rn(r0 - __half2float(h0));
    __half l1 = __float2half_rn(r1 - __half2float(h1));
    if (slot < 6) {
        int h = kvh * NG + slot;
        __half* q = q16 + (((size_t)b * NH + h) * S_LEN + s) * 256;
        q[i] = h0; q[i + 64] = h1; q[128 + i] = l0; q[192 + i] = l1;
    } else {
        __half* kv = kv16 + (((size_t)b * NKVH + kvh) * S_LEN + s) * 512;
        int base = (slot == 6) ? 0 : 256;
        kv[base + i] = h0; kv[base + 64 + i] = h1;
        kv[base + 128 + i] = l0; kv[base + 192 + i] = l1;
    }
}

// ---------------------------------------------------------------------------
// Flash attention, fp16 hi/lo 3-term, causal, GQA. BQ=128, BK=64, 256 thr.
// Pure cp.async loads from q16/kv16, double-buffered KV tiles.
// Epilogue writes triplicated ctx3 bf16 [hi|hi|lo].
// ---------------------------------------------------------------------------
#define QP2 136
#define QROWB (QP2 * 2)                 // 272 bytes per smem row
#define Q_ARR_B (128 * QROWB)           // 34816
#define KV_ARR_B (64 * QROWB)           // 17408
#define KV_STG_B (4 * KV_ARR_B)         // 69632
#define ATTN_SMEM (2 * Q_ARR_B + 2 * KV_STG_B)   // 208896

__device__ __forceinline__ u32 pack_h2(float lo, float hi) {
    u32 r;
    asm("cvt.rn.f16x2.f32 %0, %1, %2;" : "=r"(r) : "f"(hi), "f"(lo));
    return r;
}

__global__ void __launch_bounds__(256, 1)
attn_mma_kernel(const __half* __restrict__ q16, const __half* __restrict__ kv16,
                __nv_bfloat16* __restrict__ ctx3) {
    extern __shared__ __align__(16) char asm_raw[];
    const u32 sb = smem_u32(asm_raw);
    const u32 qh_b = sb;
    const u32 ql_b = sb + Q_ARR_B;
    const u32 kv0  = sb + 2 * Q_ARR_B;

    const int tid  = threadIdx.x;
    const int lane = tid & 31;
    const int wid  = tid >> 5;
    const int qt   = (int)gridDim.x - 1 - blockIdx.x;   // heavy tiles first
    const int h    = blockIdx.y;
    const int b    = blockIdx.z;
    const int kvh  = h / NG;
    const int qbase = qt * 128;

    const __half* qrow = q16 + (((size_t)b * NH + h) * S_LEN + qbase) * 256;
    const __half* kvbase = kv16 + (((size_t)b * NKVH + kvh) * S_LEN) * 512;

    // --- prologue: async-load Q (qh+ql) and KV tile 0 into stage 0 ---
#pragma unroll
    for (int t = 0; t < 16; t++) {
        int cid = tid + t * 256;            // 0..4095
        int row = cid >> 5;                 // 32 chunks per row
        int sub = cid & 31;                 // <16: qh, >=16: ql
        u32 dst = ((sub < 16) ? qh_b : ql_b) + (u32)row * QROWB + (sub & 15) * 16;
        CP16(dst, qrow + (size_t)row * 256 + sub * 8);
    }
#pragma unroll
    for (int t = 0; t < 16; t++) {
        int cid = tid + t * 256;
        int row = cid >> 6;
        int sub = cid & 63;
        int arr = sub >> 4, j = sub & 15;
        u32 dst = kv0 + (u32)arr * KV_ARR_B + (u32)row * QROWB + j * 16;
        CP16(dst, kvbase + (size_t)row * 512 + arr * 128 + j * 8);
    }
    CP_COMMIT();

    float S[8][4], O[16][4];
    float m0 = -INFINITY, m1 = -INFINITY, l0 = 0.f, l1 = 0.f;
#pragma unroll
    for (int nj = 0; nj < 16; nj++)
#pragma unroll
        for (int q = 0; q < 4; q++) O[nj][q] = 0.f;

    const u32 a_off = ((u32)(wid * 16 + (lane & 15)) * QP2 + 8 * (lane >> 4)) * 2;
    const u32 b_off = ((u32)((lane & 7) + 8 * (lane >> 4)) * QP2 + 8 * ((lane >> 3) & 1)) * 2;
    const u32 v_off = ((u32)((lane & 7) + 8 * ((lane >> 3) & 1)) * QP2 + 8 * (lane >> 4)) * 2;

    const int nkt = 2 * qt + 2;
    for (int kt = 0; kt < nkt; kt++) {
        int stg = kt & 1;
        __syncthreads();   // all warps done reading stage stg^1 (iter kt-1)
        if (kt + 1 < nkt) {
            const __half* src = kvbase + (size_t)(kt + 1) * 64 * 512;
            u32 dstb = kv0 + (u32)(stg ^ 1) * KV_STG_B;
#pragma unroll
            for (int t = 0; t < 16; t++) {
                int cid = tid + t * 256;
                int row = cid >> 6;
                int sub = cid & 63;
                int arr = sub >> 4, j = sub & 15;
                CP16(dstb + (u32)arr * KV_ARR_B + (u32)row * QROWB + j * 16,
                     src + (size_t)row * 512 + arr * 128 + j * 8);
            }
        }
        CP_COMMIT();
        CP_WAIT(1);        // stage stg (and Q on kt==0) complete
        __syncthreads();

        const u32 kh_b = kv0 + (u32)stg * KV_STG_B;
        const u32 kl_b = kh_b + KV_ARR_B;
        const u32 vh_b = kh_b + 2 * KV_ARR_B;
        const u32 vl_b = kh_b + 3 * KV_ARR_B;

        // --- scores S = Q K^T (3-term split) ---
#pragma unroll
        for (int j = 0; j < 8; j++)
#pragma unroll
            for (int q = 0; q < 4; q++) S[j][q] = 0.f;

#pragma unroll
        for (int kc = 0; kc < 8; kc++) {
            u32 ah[4], al[4];
            LDSM4(ah, qh_b + a_off + kc * 32);
            LDSM4(al, ql_b + a_off + kc * 32);
#pragma unroll
            for (int nn = 0; nn < 4; nn++) {
                u32 bh[4], bl[4];
                u32 bo = b_off + nn * (16 * QROWB) + kc * 32;
                LDSM4(bh, kh_b + bo);
                LDSM4(bl, kl_b + bo);
                mma_f16(S[2 * nn],     ah, bh);
                mma_f16(S[2 * nn],     ah, bl);
                mma_f16(S[2 * nn],     al, bh);
                mma_f16(S[2 * nn + 1], ah, bh + 2);
                mma_f16(S[2 * nn + 1], ah, bl + 2);
                mma_f16(S[2 * nn + 1], al, bh + 2);
            }
        }

        // --- causal mask (diagonal tiles only) ---
        if (kt >= 2 * qt) {
            int r0 = qbase + wid * 16 + (lane >> 2);
            int r1 = r0 + 8;
#pragma unroll
            for (int j = 0; j < 8; j++) {
                int c0 = kt * 64 + 8 * j + 2 * (lane & 3);
                if (c0 > r0)     S[j][0] = -1e30f;
                if (c0 + 1 > r0) S[j][1] = -1e30f;
                if (c0 > r1)     S[j][2] = -1e30f;
                if (c0 + 1 > r1) S[j][3] = -1e30f;
            }
        }

        // --- online softmax (rows warp-local, 4 lanes per row) ---
        float rmax0 = -INFINITY, rmax1 = -INFINITY;
#pragma unroll
        for (int j = 0; j < 8; j++) {
            rmax0 = fmaxf(rmax0, fmaxf(S[j][0], S[j][1]));
            rmax1 = fmaxf(rmax1, fmaxf(S[j][2], S[j][3]));
        }
        rmax0 = fmaxf(rmax0, __shfl_xor_sync(0xffffffffu, rmax0, 1));
        rmax0 = fmaxf(rmax0, __shfl_xor_sync(0xffffffffu, rmax0, 2));
        rmax1 = fmaxf(rmax1, __shfl_xor_sync(0xffffffffu, rmax1, 1));
        rmax1 = fmaxf(rmax1, __shfl_xor_sync(0xffffffffu, rmax1, 2));
        float mn0 = fmaxf(m0, rmax0), mn1 = fmaxf(m1, rmax1);
        float al0 = __expf(m0 - mn0), al1 = __expf(m1 - mn1);
        float rs0 = 0.f, rs1 = 0.f;
#pragma unroll
        for (int j = 0; j < 8; j++) {
            S[j][0] = __expf(S[j][0] - mn0);
            S[j][1] = __expf(S[j][1] - mn0);
            S[j][2] = __expf(S[j][2] - mn1);
            S[j][3] = __expf(S[j][3] - mn1);
            rs0 += S[j][0] + S[j][1];
            rs1 += S[j][2] + S[j][3];
        }
        rs0 += __shfl_xor_sync(0xffffffffu, rs0, 1);
        rs0 += __shfl_xor_sync(0xffffffffu, rs0, 2);
        rs1 += __shfl_xor_sync(0xffffffffu, rs1, 1);
        rs1 += __shfl_xor_sync(0xffffffffu, rs1, 2);
        l0 = l0 * al0 + rs0;
        l1 = l1 * al1 + rs1;
        m0 = mn0; m1 = mn1;
#pragma unroll
        for (int nj = 0; nj < 16; nj++) {
            O[nj][0] *= al0; O[nj][1] *= al0;
            O[nj][2] *= al1; O[nj][3] *= al1;
        }

        // --- O += P V (3-term split, P frags in-register) ---
#pragma unroll
        for (int kc2 = 0; kc2 < 4; kc2++) {
            int j0 = 2 * kc2, j1 = 2 * kc2 + 1;
            u32 pa[4], pl[4];
            float e[4][2] = {{S[j0][0], S[j0][1]}, {S[j0][2], S[j0][3]},
                             {S[j1][0], S[j1][1]}, {S[j1][2], S[j1][3]}};
#pragma unroll
            for (int q = 0; q < 4; q++) {
                __half h0 = __float2half_rn(e[q][0]);
                __half h1 = __float2half_rn(e[q][1]);
                pa[q] = pack_h2((float)__half2float(h0), (float)__half2float(h1));
                pl[q] = pack_h2(e[q][0] - __half2float(h0), e[q][1] - __half2float(h1));
            }
#pragma unroll
            for (int nn = 0; nn < 8; nn++) {
                u32 vh[4], vl[4];
                u32 vo = v_off + kc2 * (16 * QROWB) + nn * 32;
                LDSM4T(vh, vh_b + vo);
                LDSM4T(vl, vl_b + vo);
                mma_f16(O[2 * nn],     pa, vh);
                mma_f16(O[2 * nn],     pa, vl);
                mma_f16(O[2 * nn],     pl, vh);
                mma_f16(O[2 * nn + 1], pa, vh + 2);
                mma_f16(O[2 * nn + 1], pa, vl + 2);
                mma_f16(O[2 * nn + 1], pl, vh + 2);
            }
        }
    }

    // --- epilogue: normalize + write ctx3 bf16 [hi|hi|lo] directly ---
    float inv0 = 1.0f / l0, inv1 = 1.0f / l1;
    int r0 = qbase + wid * 16 + (lane >> 2);
    __nv_bfloat16* d0 = ctx3 + ((size_t)b * S_LEN + r0) * K3 + h * HD + 2 * (lane & 3);
    __nv_bfloat16* d1 = d0 + (size_t)8 * K3;
#pragma unroll
    for (int nj = 0; nj < 16; nj++) {
        float a0 = O[nj][0] * inv0, a1 = O[nj][1] * inv0;
        float b0 = O[nj][2] * inv1, b1 = O[nj][3] * inv1;
        __nv_bfloat16 ha0 = __float2bfloat16(a0), ha1 = __float2bfloat16(a1);
        __nv_bfloat16 hb0 = __float2bfloat16(b0), hb1 = __float2bfloat16(b1);
        u32 hp0 = (u32)__bfloat16_as_ushort(ha0) | ((u32)__bfloat16_as_ushort(ha1) << 16);
        u32 hp1 = (u32)__bfloat16_as_ushort(hb0) | ((u32)__bfloat16_as_ushort(hb1) << 16);
        u32 lp0 = (u32)__bfloat16_as_ushort(__float2bfloat16(a0 - __bfloat162float(ha0)))
                | ((u32)__bfloat16_as_ushort(__float2bfloat16(a1 - __bfloat162float(ha1))) << 16);
        u32 lp1 = (u32)__bfloat16_as_ushort(__float2bfloat16(b0 - __bfloat162float(hb0)))
                | ((u32)__bfloat16_as_ushort(__float2bfloat16(b1 - __bfloat162float(hb1))) << 16);
        *(u32*)(d0 + 8 * nj)              = hp0;
        *(u32*)(d0 + HIDDEN + 8 * nj)     = hp0;
        *(u32*)(d0 + 2 * HIDDEN + 8 * nj) = lp0;
        *(u32*)(d1 + 8 * nj)              = hp1;
        *(u32*)(d1 + HIDDEN + 8 * nj)     = hp1;
        *(u32*)(d1 + 2 * HIDDEN + 8 * nj) = lp1;
    }
}

// ---------------------------------------------------------------------------
extern "C" void kernel_launch(void* const* d_in, const int* in_sizes, int n_in,
                              void* d_out, int out_size) {
    const float* x    = (const float*)d_in[0];   // [2,2048,6144]
    const float* Wqkv = (const float*)d_in[1];   // [8192,6144]
    const float* Wo   = (const float*)d_in[2];   // [6144,6144]
    float* out = (float*)d_out;                  // [2,2048,6144]

    float* qkv = nullptr;
    __nv_bfloat16 *a3x = nullptr, *wqkv3 = nullptr, *wo3 = nullptr, *ctx3 = nullptr;
    __half *q16 = nullptr, *kv16 = nullptr;
    cudaGetSymbolAddress((void**)&qkv,   g_qkv);
    cudaGetSymbolAddress((void**)&a3x,   g_a3x);
    cudaGetSymbolAddress((void**)&wqkv3, g_wqkv3);
    cudaGetSymbolAddress((void**)&wo3,   g_wo3);
    cudaGetSymbolAddress((void**)&ctx3,  g_ctx3);
    cudaGetSymbolAddress((void**)&q16,   g_q16);
    cudaGetSymbolAddress((void**)&kv16,  g_kv16);

    cudaFuncSetAttribute(gemm_mma_kernel,
                         cudaFuncAttributeMaxDynamicSharedMemorySize, GEMM_SMEM);
    cudaFuncSetAttribute(attn_mma_kernel,
                         cudaFuncAttributeMaxDynamicSharedMemorySize, ATTN_SMEM);

    // 0) bf16 hi/lo splits (triplicated linear layouts)
    int t4x = 4096 * (HIDDEN / 4);
    int t4q = 8192 * (HIDDEN / 4);
    int t4o = 6144 * (HIDDEN / 4);
    split3_kernel<<<(t4x + 255) / 256, 256>>>(x,    a3x,   t4x, 0);
    split3_kernel<<<(t4q + 255) / 256, 256>>>(Wqkv, wqkv3, t4q, 1);
    split3_kernel<<<(t4o + 255) / 256, 256>>>(Wo,   wo3,   t4o, 1);

    // 1) QKV projection: [4096,8192]  (MT=32, NT=64)
    gemm_mma_kernel<<<32 * 64, 256, GEMM_SMEM>>>(a3x, wqkv3, qkv, 64, 8192);

    // 2) RoPE + scale + fp16 hi/lo split of q/k/v
    rope16_kernel<<<(4096 * 8 * 8 * 64) / 256, 256>>>(qkv, q16, kv16);

    // 3) Flash attention (tensor cores, async loads) -> ctx3 bf16 [hi|hi|lo]
    attn_mma_kernel<<<dim3(16, NH, 2), 256, ATTN_SMEM>>>(q16, kv16, ctx3);

    // 4) output projection: [4096,6144]  (MT=32, NT=48)
    gemm_mma_kernel<<<32 * 48, 256, GEMM_SMEM>>>(ctx3, wo3, out, 48, 6144);
}